// round 13
// baseline (speedup 1.0000x reference)
#include <cuda_runtime.h>
#include <cstdint>

// CSCFCLayer: out[b][n] = sum_{f<64} x[b][(n+f)%C] * kernel[(n+f)%C][n] + bias[n]
// B=128, C=N=8192, F=64, fp32.
//
// v13 = v11 (band-trimmed m16n8k8 tf32, grid 128, 1024 thr, direct-STG epilogue)
//      + two-stage k-pipeline (split at k=64):
//  - A: two cp.async commit groups; stage-0 starts after wait_group 1 (A1 in flight).
//  - B rows 64..127: LDG to registers up front, STS at the stage boundary ->
//    second DRAM exposure hidden behind stage-0 MMAs.
//  - Stage split per warp: steps with 16nw+8s < 64 in stage 0, rest in stage 1.

#define CDIM 8192
#define NDIM 8192
#define NT 64
#define THREADS 1024
#define ASTRIDE 132
#define BSTRIDE 72
#define A_FLOATS (128 * ASTRIDE)
#define SMEM_NEED ((A_FLOATS + 128 * BSTRIDE) * 4)

__device__ __forceinline__ uint32_t f2tf(float f) {
    uint32_t r;
    asm("cvt.rna.tf32.f32 %0, %1;" : "=r"(r) : "f"(f));
    return r;
}

__device__ __forceinline__ void mma_tf32(float* c,
                                         uint32_t a0, uint32_t a1,
                                         uint32_t a2, uint32_t a3,
                                         uint32_t b0, uint32_t b1) {
    asm volatile(
        "mma.sync.aligned.m16n8k8.row.col.f32.tf32.tf32.f32 "
        "{%0,%1,%2,%3}, {%4,%5,%6,%7}, {%8,%9}, {%0,%1,%2,%3};"
        : "+f"(c[0]), "+f"(c[1]), "+f"(c[2]), "+f"(c[3])
        : "r"(a0), "r"(a1), "r"(a2), "r"(a3), "r"(b0), "r"(b1));
}

extern "C" __global__ void __launch_bounds__(THREADS, 1)
cscfc_mma_kernel(const float* __restrict__ x,
                 const float* __restrict__ w,
                 const float* __restrict__ bias,
                 float* __restrict__ out)
{
    extern __shared__ float sm[];
    float* As = sm;               // [128 b][ASTRIDE] raw fp32 x window
    float* Bs = sm + A_FLOATS;    // [128 k][BSTRIDE] banded tf32 weights, [k][n]

    const int tid  = threadIdx.x;
    const int lane = tid & 31;
    const int wid  = tid >> 5;
    const int n0   = blockIdx.x * NT;

    const int mw = wid & 7;       // row group (16 rows)
    const int nw = wid >> 3;      // col group (16 cols)
    const int g  = lane >> 2;
    const int tg = lane & 3;

    // ---- A fill: stage 0 (k 0..63) then stage 1 (k 64..127), separate groups. ----
    {
        const unsigned as_u = (unsigned)__cvta_generic_to_shared(As);
        const int b = tid >> 3;
        const int q = tid & 7;
#pragma unroll
        for (int kc = 0; kc < 2; ++kc) {
            const int col = kc * 32 + q * 4;
            const int c = (n0 + col) & (CDIM - 1);
            asm volatile("cp.async.cg.shared.global [%0], [%1], 16;"
                         :: "r"(as_u + (unsigned)(b * ASTRIDE + col) * 4u),
                            "l"(x + (size_t)b * CDIM + c) : "memory");
        }
        asm volatile("cp.async.commit_group;" ::: "memory");
#pragma unroll
        for (int kc = 2; kc < 4; ++kc) {
            const int col = kc * 32 + q * 4;
            const int c = (n0 + col) & (CDIM - 1);
            asm volatile("cp.async.cg.shared.global [%0], [%1], 16;"
                         :: "r"(as_u + (unsigned)(b * ASTRIDE + col) * 4u),
                            "l"(x + (size_t)b * CDIM + c) : "memory");
        }
        asm volatile("cp.async.commit_group;" ::: "memory");
    }

    // ---- bias prefetch. ----
    const float2 bz0 = *(const float2*)(bias + n0 + nw * 16 + tg * 2);
    const float2 bz1 = *(const float2*)(bias + n0 + nw * 16 + 8 + tg * 2);

    // ---- B loads: B0 (rows 0..63, staged now) + B1 (rows 64..127, regs until
    //      stage boundary). Predicated LDG skips all-out-of-band float4s. ----
    const int cl0 = tid >> 4;             // 0..63
    const int cl1 = cl0 + 64;             // 64..127
    const int nb  = (tid & 15) * 4;
    float4 wv0, wv1;
    {
        const int r0 = (n0 + cl0) & (CDIM - 1);
        const int r1 = (n0 + cl1) & (CDIM - 1);
        const bool va0 = (cl0 >= nb) && (cl0 <= nb + 66);
        const bool va1 = (cl1 >= nb) && (cl1 <= nb + 66);
        wv0 = va0 ? *(const float4*)(w + (size_t)r0 * NDIM + n0 + nb)
                  : make_float4(0.f, 0.f, 0.f, 0.f);
        wv1 = va1 ? *(const float4*)(w + (size_t)r1 * NDIM + n0 + nb)
                  : make_float4(0.f, 0.f, 0.f, 0.f);
    }
    {
        uint4 st;
        st.x = ((unsigned)(cl0 - nb)     < 64u) ? f2tf(wv0.x) : 0u;
        st.y = ((unsigned)(cl0 - nb - 1) < 64u) ? f2tf(wv0.y) : 0u;
        st.z = ((unsigned)(cl0 - nb - 2) < 64u) ? f2tf(wv0.z) : 0u;
        st.w = ((unsigned)(cl0 - nb - 3) < 64u) ? f2tf(wv0.w) : 0u;
        *(uint4*)&Bs[cl0 * BSTRIDE + nb] = st;
    }
    asm volatile("cp.async.wait_group 1;" ::: "memory");   // A0 complete
    __syncthreads();

    // ---- Stage 0: steps with global k8 index ks = 2nw + s < 8. ----
    float acc[2][4] = {{0.f, 0.f, 0.f, 0.f}, {0.f, 0.f, 0.f, 0.f}};
    const int split = 8 - 2 * nw;         // stage-0 step count (8,6,4,2)

    const float*    Ap = As + (mw * 16 + g) * ASTRIDE + tg + nw * 16;
    const uint32_t* Bq = (const uint32_t*)Bs + (nw * 16 + tg) * BSTRIDE + nw * 16 + g;
    const float*    ap = Ap;
    const uint32_t* bq = Bq;

    for (int s = 0; s < split; ++s) {
        const uint32_t a0 = __float_as_uint(ap[0]);
        const uint32_t a1 = __float_as_uint(ap[8 * ASTRIDE]);
        const uint32_t a2 = __float_as_uint(ap[4]);
        const uint32_t a3 = __float_as_uint(ap[8 * ASTRIDE + 4]);
        const uint32_t b0 = bq[0];
        const uint32_t b1 = bq[4 * BSTRIDE];
        const uint32_t b2 = bq[8];
        const uint32_t b3 = bq[4 * BSTRIDE + 8];
        mma_tf32(acc[0], a0, a1, a2, a3, b0, b1);
        mma_tf32(acc[1], a0, a1, a2, a3, b2, b3);
        ap += 8;
        bq += 8 * BSTRIDE;
    }

    // ---- Stage boundary: store B1 (regs -> smem), A1 visible, barrier. ----
    {
        uint4 st;
        st.x = ((unsigned)(cl1 - nb)     < 64u) ? f2tf(wv1.x) : 0u;
        st.y = ((unsigned)(cl1 - nb - 1) < 64u) ? f2tf(wv1.y) : 0u;
        st.z = ((unsigned)(cl1 - nb - 2) < 64u) ? f2tf(wv1.z) : 0u;
        st.w = ((unsigned)(cl1 - nb - 3) < 64u) ? f2tf(wv1.w) : 0u;
        *(uint4*)&Bs[cl1 * BSTRIDE + nb] = st;
    }
    asm volatile("cp.async.wait_group 0;" ::: "memory");   // A1 complete
    __syncthreads();

    // ---- Stage 1: remaining steps. ----
    for (int s = split; s < 10; ++s) {
        const uint32_t a0 = __float_as_uint(ap[0]);
        const uint32_t a1 = __float_as_uint(ap[8 * ASTRIDE]);
        const uint32_t a2 = __float_as_uint(ap[4]);
        const uint32_t a3 = __float_as_uint(ap[8 * ASTRIDE + 4]);
        const uint32_t b0 = bq[0];
        const uint32_t b1 = bq[4 * BSTRIDE];
        const uint32_t b2 = bq[8];
        const uint32_t b3 = bq[4 * BSTRIDE + 8];
        mma_tf32(acc[0], a0, a1, a2, a3, b0, b1);
        mma_tf32(acc[1], a0, a1, a2, a3, b2, b3);
        ap += 8;
        bq += 8 * BSTRIDE;
    }

    // ---- Epilogue: direct STG.64 + bias. ----
    {
        const int row = mw * 16 + g;
        const int c0  = n0 + nw * 16 + tg * 2;
        float* o0 = out + (size_t)row * NDIM + c0;
        float* o1 = out + (size_t)(row + 8) * NDIM + c0;
        *(float2*)o0       = make_float2(acc[0][0] + bz0.x, acc[0][1] + bz0.y);
        *(float2*)o1       = make_float2(acc[0][2] + bz0.x, acc[0][3] + bz0.y);
        *(float2*)(o0 + 8) = make_float2(acc[1][0] + bz1.x, acc[1][1] + bz1.y);
        *(float2*)(o1 + 8) = make_float2(acc[1][2] + bz1.x, acc[1][3] + bz1.y);
    }
}

extern "C" void kernel_launch(void* const* d_in, const int* in_sizes, int n_in,
                              void* d_out, int out_size) {
    const float* x    = (const float*)d_in[0];
    const float* w    = (const float*)d_in[1];
    const float* bias = (const float*)d_in[2];
    float* out        = (float*)d_out;

    cudaFuncSetAttribute(cscfc_mma_kernel,
                         cudaFuncAttributeMaxDynamicSharedMemorySize, SMEM_NEED);
    cscfc_mma_kernel<<<NDIM / NT, THREADS, SMEM_NEED>>>(x, w, bias, out);
}